// round 12
// baseline (speedup 1.0000x reference)
#include <cuda_runtime.h>
#include <cuda_bf16.h>
#include <math.h>

// Problem constants
#define SEQ   2048
#define INDIM 256
#define H     512
#define CTAS_PER_SIDE 64
#define TOTAL_CTAS    128
#define RING  64
#define NTHREADS 384        // warps 0-3 producers, warps 4-11 consumers

// ---------------- device scratch (static: no allocation allowed) ----------------
__device__ __align__(16) float g_x[2][SEQ][INDIM];    // gathered embeddings, 4 MB
// Packed hidden state: [side][buf][unit] = {tag16 << 16 | bf16(h)}
__device__ __align__(16) unsigned g_hp[2][2][H];

// ---------------- packed publish/poll helpers ----------------
__device__ __forceinline__ void store_h(unsigned* p, float v, unsigned tag) {
    unsigned hb = (unsigned)__bfloat16_as_ushort(__float2bfloat16(v));
    unsigned u = (tag << 16) | hb;
    asm volatile("st.global.cg.u32 [%0], %1;" :: "l"(p), "r"(u) : "memory");
}
// Pipelined poll: keep two independent samples in flight so the sampling phase
// is shorter than a full L2 round trip. Returns packed bf16x2 (lo=u0, hi=u1).
__device__ __forceinline__ unsigned poll_h2(const unsigned* p, unsigned tag) {
    unsigned a0, b0, a1, b1;
    asm volatile("ld.global.cg.v2.u32 {%0,%1}, [%2];" : "=r"(a0), "=r"(b0) : "l"(p) : "memory");
    asm volatile("ld.global.cg.v2.u32 {%0,%1}, [%2];" : "=r"(a1), "=r"(b1) : "l"(p) : "memory");
    while (true) {
        if (((a0 >> 16) == tag) && ((b0 >> 16) == tag))
            return (a0 & 0xFFFFu) | (b0 << 16);
        asm volatile("ld.global.cg.v2.u32 {%0,%1}, [%2];" : "=r"(a0), "=r"(b0) : "l"(p) : "memory");
        if (((a1 >> 16) == tag) && ((b1 >> 16) == tag))
            return (a1 & 0xFFFFu) | (b1 << 16);
        asm volatile("ld.global.cg.v2.u32 {%0,%1}, [%2];" : "=r"(a1), "=r"(b1) : "l"(p) : "memory");
    }
}

__device__ __forceinline__ unsigned b2u(__nv_bfloat162 v) { return *(unsigned*)&v; }
__device__ __forceinline__ __nv_bfloat162 u2b(unsigned u) { return *(__nv_bfloat162*)&u; }

// fast activations (ex2-based, ~1e-6 rel err)
__device__ __forceinline__ float fast_tanh(float x) {
    return 1.0f - 2.0f / (__expf(2.0f * x) + 1.0f);
}

// ---------------- kernel 0: gather embeddings + reset packed state ----------------
// Token indices are int32 (JAX materializes jnp.int64 as int32 with x64 disabled).
__global__ void __launch_bounds__(256) init_gather(const int* __restrict__ lidx,
                                                   const int* __restrict__ ridx,
                                                   const float* __restrict__ emb) {
    int bx = blockIdx.x;              // 0..4095
    int side = bx >> 11;
    int t = bx & (SEQ - 1);
    const int* idxp = side ? ridx : lidx;
    long long tok = (long long)idxp[t];
    g_x[side][t][threadIdx.x] = emb[tok * (long long)INDIM + threadIdx.x];

    if (bx == 0) {
        int i = threadIdx.x;          // 0..255
        for (int s = 0; s < 2; s++) {
            // buf0: tag 0, h = bf16(0) -> word 0. buf1: sentinel tag 0xFFFF.
            g_hp[s][0][2 * i]     = 0u;
            g_hp[s][0][2 * i + 1] = 0u;
            g_hp[s][1][2 * i]     = 0xFFFF0000u;
            g_hp[s][1][2 * i + 1] = 0xFFFF0000u;
        }
    }
}

// ---------------- kernel 1: fused producer/consumer persistent scan ----------------
// 128 CTAs x 384 threads. Warps 0-3 produce xp into an SMEM ring ~64 steps
// ahead. Warps 4-11 (one per hidden unit) run the LSTM step with a
// gate-per-8-lane-group layout: lane L (gate L>>3, idx L&7) does a 64-wide
// bf16x2 dot for its gate; reduction is 3 xor-shfls within the group.
__global__ void __launch_bounds__(NTHREADS, 1) scan_kernel(const float* __restrict__ W_ih,
                                                           const float* __restrict__ W_hh,
                                                           const float* __restrict__ b_ih,
                                                           const float* __restrict__ b_hh,
                                                           float* __restrict__ out) {
    const int side = blockIdx.x >> 6;
    const int cta  = blockIdx.x & 63;
    const int wid  = threadIdx.x >> 5;
    const int lane = threadIdx.x & 31;
    const unsigned FULL = 0xFFFFFFFFu;

    // ---- shared state (16B-aligned: several arrays are read with uint4/float4) ----
    __shared__ __align__(16) unsigned wpcT[128][32];  // producer W_ih cols, bf16x2
    __shared__ __align__(16) unsigned xstage[4][128]; // per producer warp: x[t] bf16x2
    __shared__ __align__(16) unsigned sh2[2][H / 2];  // double-buffered staged h words
    __shared__ __align__(16) float    ring[RING][32]; // xp ring: [t mod 64][col]
    __shared__ float    bias_s[32];
    __shared__ float    sred[8];
    __shared__ volatile int ring_tag[RING];
    __shared__ volatile int scons;                    // last step fully consumed

    // ---- cooperative setup (all 384 threads) ----
    // wpcT[p][c] = bf16x2 of W_ih[row(c)][2p], [2p+1]; row(c) = (c/8)*512 + cta*8 + (c%8)
    for (int idx = threadIdx.x; idx < 128 * 32; idx += NTHREADS) {
        int c = idx & 31;
        int p = idx >> 5;
        int row = (c >> 3) * H + cta * 8 + (c & 7);
        float2 wv = *(const float2*)(W_ih + (size_t)row * INDIM + 2 * p);
        wpcT[p][c] = b2u(__floats2bfloat162_rn(wv.x, wv.y));
    }
    if (threadIdx.x < 32) {
        int c = threadIdx.x;
        int row = (c >> 3) * H + cta * 8 + (c & 7);
        bias_s[c] = b_ih[row] + b_hh[row];
    }
    for (int s = threadIdx.x; s < RING; s += NTHREADS) ring_tag[s] = -1;
    if (threadIdx.x == 0) scons = -1;
    __syncthreads();   // the ONLY full-CTA barrier

    if (wid < 4) {
        // ================= PRODUCER =================
        const int p = wid;
        for (int t = p; t < SEQ; t += 4) {
            while (scons < t - RING) { __nanosleep(128); }   // backoff spin

            // load x[t][lane*8 .. +7], convert to 4 bf16x2, stage for broadcast
            const float4* xp4 = (const float4*)&g_x[side][t][lane * 8];
            float4 v1 = __ldg(xp4);
            float4 v2 = __ldg(xp4 + 1);
            xstage[p][lane * 4 + 0] = b2u(__floats2bfloat162_rn(v1.x, v1.y));
            xstage[p][lane * 4 + 1] = b2u(__floats2bfloat162_rn(v1.z, v1.w));
            xstage[p][lane * 4 + 2] = b2u(__floats2bfloat162_rn(v2.x, v2.y));
            xstage[p][lane * 4 + 3] = b2u(__floats2bfloat162_rn(v2.z, v2.w));
            __syncwarp();

            // lane = col; dot over 128 k-pairs, 4 bf16x2 partial accumulators
            __nv_bfloat162 a0 = __floats2bfloat162_rn(0.f, 0.f);
            __nv_bfloat162 a1 = a0, a2 = a0, a3 = a0;
            #pragma unroll
            for (int s = 0; s < 32; s++) {
                uint4 xv = *(const uint4*)&xstage[p][s * 4];   // broadcast (16B)
                a0 = __hfma2(u2b(wpcT[s * 4 + 0][lane]), u2b(xv.x), a0);
                a1 = __hfma2(u2b(wpcT[s * 4 + 1][lane]), u2b(xv.y), a1);
                a2 = __hfma2(u2b(wpcT[s * 4 + 2][lane]), u2b(xv.z), a2);
                a3 = __hfma2(u2b(wpcT[s * 4 + 3][lane]), u2b(xv.w), a3);
            }
            float sum = (__low2float(a0) + __high2float(a0))
                      + (__low2float(a1) + __high2float(a1))
                      + (__low2float(a2) + __high2float(a2))
                      + (__low2float(a3) + __high2float(a3))
                      + bias_s[lane];
            ring[t & (RING - 1)][lane] = sum;
            __syncwarp();
            if (lane == 0) {
                asm volatile("membar.cta;" ::: "memory");
                ring_tag[t & (RING - 1)] = t;
            }
            __syncwarp();   // reads of xstage done before next iteration restages
        }
        return;
    }

    // ================= CONSUMER =================
    const int cw    = wid - 4;                  // 0..7
    const int jj    = cw;                       // unit within CTA
    const int j     = cta * 8 + jj;             // hidden unit 0..511
    const int tid_c = threadIdx.x - 128;        // 0..255

    const int mygate = lane >> 3;               // 0:i 1:f 2:g 3:o (8 lanes per gate)
    const int myidx  = lane & 7;                // h chunk index within gate

    // recurrent weights: lane holds W_hh[mygate*H + j][myidx*64 .. +63] as 32 bf16x2
    unsigned w2[32];
    {
        const float2* row = (const float2*)(W_hh + (size_t)(mygate * H + j) * H + myidx * 64);
        #pragma unroll
        for (int k = 0; k < 32; k++) {
            float2 pv = row[k];
            w2[k] = b2u(__floats2bfloat162_rn(pv.x, pv.y));
        }
    }

    float c = 0.0f;                             // live in lane 0 only

    for (int t = 0; t < SEQ; t++) {
        const int rb = t & 1;
        const int slot = t & (RING - 1);

        // xp from SMEM ring (producers run ~64 steps ahead; normally instant)
        while (ring_tag[slot] != t) { }
        float xg = ring[slot][mygate * 8 + jj];

        // poll own two packed units; stage bf16x2 word directly
        unsigned hp = poll_h2(&g_hp[side][rb][2 * tid_c], (unsigned)t);
        sh2[rb][tid_c] = hp;
        asm volatile("bar.sync 1, 256;" ::: "memory");
        if (tid_c == 0) scons = t;              // all consumers past ring read

        // lane reads its 64 h values = 32 bf16x2 words (128B) from SMEM,
        // dots against its gate's weights; 4 accumulator chains of 8.
        const uint4* hptr = (const uint4*)&sh2[rb][myidx * 32];
        __nv_bfloat162 a0 = __floats2bfloat162_rn(0.f, 0.f);
        __nv_bfloat162 a1 = a0, a2 = a0, a3 = a0;
        #pragma unroll
        for (int q = 0; q < 8; q++) {
            uint4 hv = hptr[q];
            a0 = __hfma2(u2b(w2[q * 4 + 0]), u2b(hv.x), a0);
            a1 = __hfma2(u2b(w2[q * 4 + 1]), u2b(hv.y), a1);
            a2 = __hfma2(u2b(w2[q * 4 + 2]), u2b(hv.z), a2);
            a3 = __hfma2(u2b(w2[q * 4 + 3]), u2b(hv.w), a3);
        }
        float r = (__low2float(a0) + __high2float(a0))
                + (__low2float(a1) + __high2float(a1))
                + (__low2float(a2) + __high2float(a2))
                + (__low2float(a3) + __high2float(a3));

        // 3-round reduce within the 8-lane gate group
        r += __shfl_xor_sync(FULL, r, 4);
        r += __shfl_xor_sync(FULL, r, 2);
        r += __shfl_xor_sync(FULL, r, 1);

        // distributed activation: gate 2 -> tanh, else sigmoid
        float x = r + xg;
        bool is_tanh = (mygate == 2);
        float e = __expf(is_tanh ? (2.0f * x) : (-x));
        float num = is_tanh ? (e - 1.0f) : 1.0f;
        float act = num / (e + 1.0f);

        // lane 0 gathers gates: i lane 0, f lane 8, g lane 16, o lane 24
        float gf = __shfl_sync(FULL, act, 8);
        float gg = __shfl_sync(FULL, act, 16);
        float go = __shfl_sync(FULL, act, 24);
        if (lane == 0) {
            c = gf * c + act * gg;              // act = gi in lane 0
            float hval = go * fast_tanh(c);
            store_h(&g_hp[side][rb ^ 1][j], hval, (unsigned)(t + 1));
        }
    }

    // Final: block 0's consumers poll both sides' final tags (SEQ=2048) and reduce.
    if (blockIdx.x == 0) {
        unsigned lp = poll_h2(&g_hp[0][0][2 * tid_c], (unsigned)SEQ);
        unsigned rp = poll_h2(&g_hp[1][0][2 * tid_c], (unsigned)SEQ);
        __nv_bfloat162 lv = u2b(lp), rv = u2b(rp);
        float sv = fabsf(__low2float(lv) - __low2float(rv))
                 + fabsf(__high2float(lv) - __high2float(rv));
        #pragma unroll
        for (int off = 16; off > 0; off >>= 1)
            sv += __shfl_xor_sync(FULL, sv, off);
        if (lane == 0) sred[cw] = sv;
        asm volatile("bar.sync 1, 256;" ::: "memory");
        if (tid_c == 0) {
            float s = 0.0f;
            #pragma unroll
            for (int wdx = 0; wdx < 8; wdx++) s += sred[wdx];
            out[0] = expf(-s);
        }
    }
}

// ---------------- launch ----------------
extern "C" void kernel_launch(void* const* d_in, const int* in_sizes, int n_in,
                              void* d_out, int out_size) {
    const int* lidx = (const int*)d_in[0];
    const int* ridx = (const int*)d_in[1];
    const float* emb  = (const float*)d_in[2];
    const float* W_ih = (const float*)d_in[3];
    const float* W_hh = (const float*)d_in[4];
    const float* b_ih = (const float*)d_in[5];
    const float* b_hh = (const float*)d_in[6];
    float* out = (float*)d_out;

    init_gather<<<4096, 256>>>(lidx, ridx, emb);
    scan_kernel<<<TOTAL_CTAS, NTHREADS>>>(W_ih, W_hh, b_ih, b_hh, out);
}

// round 15
// speedup vs baseline: 2.0750x; 2.0750x over previous
#include <cuda_runtime.h>
#include <cuda_bf16.h>
#include <math.h>

// Problem constants
#define SEQ   2048
#define INDIM 256
#define H     512
#define CTAS_PER_SIDE 64
#define TOTAL_CTAS    128
#define RING  64
#define NTHREADS 384        // warps 0-3 producers, warps 4-11 consumers
#define SPIN_CAP 400000000u // termination guard: unreachable in correct runs

// ---------------- device scratch (static: no allocation allowed) ----------------
__device__ __align__(16) float g_x[2][SEQ][INDIM];    // gathered embeddings, 4 MB
// Packed hidden state: [side][buf][unit] = {tag16 << 16 | bf16(h)}
__device__ __align__(16) unsigned g_hp[2][2][H];

// ---------------- packed publish/poll helpers ----------------
__device__ __forceinline__ void store_h(unsigned* p, float v, unsigned tag) {
    unsigned hb = (unsigned)__bfloat16_as_ushort(__float2bfloat16(v));
    unsigned u = (tag << 16) | hb;
    asm volatile("st.global.cg.u32 [%0], %1;" :: "l"(p), "r"(u) : "memory");
}
// Single-sample poll (R10-proven), with a termination cap: in a correct run the
// cap is never reached; if a pathological stall exists the kernel exits with a
// wrong answer instead of hanging the container (diagnosable via rel_err).
__device__ __forceinline__ unsigned poll_h2(const unsigned* p, unsigned tag) {
    unsigned a, b;
    unsigned spins = 0;
    do {
        asm volatile("ld.global.cg.v2.u32 {%0,%1}, [%2];"
                     : "=r"(a), "=r"(b) : "l"(p) : "memory");
        if (++spins >= SPIN_CAP) break;
    } while ((a >> 16) != tag || (b >> 16) != tag);
    return (a & 0xFFFFu) | (b << 16);
}

__device__ __forceinline__ unsigned b2u(__nv_bfloat162 v) { return *(unsigned*)&v; }
__device__ __forceinline__ __nv_bfloat162 u2b(unsigned u) { return *(__nv_bfloat162*)&u; }

// fast activations (ex2-based, ~1e-6 rel err)
__device__ __forceinline__ float fast_tanh(float x) {
    return 1.0f - 2.0f / (__expf(2.0f * x) + 1.0f);
}

// ---------------- kernel 0: gather embeddings + reset packed state ----------------
// Token indices are int32 (JAX materializes jnp.int64 as int32 with x64 disabled).
__global__ void __launch_bounds__(256) init_gather(const int* __restrict__ lidx,
                                                   const int* __restrict__ ridx,
                                                   const float* __restrict__ emb) {
    int bx = blockIdx.x;              // 0..4095
    int side = bx >> 11;
    int t = bx & (SEQ - 1);
    const int* idxp = side ? ridx : lidx;
    long long tok = (long long)idxp[t];
    g_x[side][t][threadIdx.x] = emb[tok * (long long)INDIM + threadIdx.x];

    if (bx == 0) {
        int i = threadIdx.x;          // 0..255
        for (int s = 0; s < 2; s++) {
            // buf0: tag 0, h = bf16(0) -> word 0. buf1: sentinel tag 0xFFFF.
            g_hp[s][0][2 * i]     = 0u;
            g_hp[s][0][2 * i + 1] = 0u;
            g_hp[s][1][2 * i]     = 0xFFFF0000u;
            g_hp[s][1][2 * i + 1] = 0xFFFF0000u;
        }
    }
}

// ---------------- kernel 1: fused producer/consumer persistent scan ----------------
// 128 CTAs x 384 threads. Warps 0-3 produce xp into an SMEM ring ~64 steps
// ahead. Warps 4-11 (one per hidden unit): gate-per-8-lane-group layout with an
// XOR/rotate swizzle on the staged-h reads so each 16B LDS is conflict-free.
// ALL spin loops carry termination caps (hang-proof by construction).
__global__ void __launch_bounds__(NTHREADS, 1) scan_kernel(const float* __restrict__ W_ih,
                                                           const float* __restrict__ W_hh,
                                                           const float* __restrict__ b_ih,
                                                           const float* __restrict__ b_hh,
                                                           float* __restrict__ out) {
    const int side = blockIdx.x >> 6;
    const int cta  = blockIdx.x & 63;
    const int wid  = threadIdx.x >> 5;
    const int lane = threadIdx.x & 31;
    const unsigned FULL = 0xFFFFFFFFu;

    // ---- shared state (16B-aligned: several arrays are read with uint4/float4) ----
    __shared__ __align__(16) unsigned wpcT[128][32];  // producer W_ih cols, bf16x2
    __shared__ __align__(16) unsigned xstage[4][128]; // per producer warp: x[t] bf16x2
    __shared__ __align__(16) unsigned sh2[2][H / 2];  // double-buffered staged h words
    __shared__ __align__(16) float    ring[RING][32]; // xp ring: [t mod 64][col]
    __shared__ float    bias_s[32];
    __shared__ float    sred[8];
    __shared__ volatile int ring_tag[RING];
    __shared__ volatile int scons;                    // last step fully consumed

    // ---- cooperative setup (all 384 threads) ----
    // wpcT[p][c] = bf16x2 of W_ih[row(c)][2p], [2p+1]; row(c) = (c/8)*512 + cta*8 + (c%8)
    for (int idx = threadIdx.x; idx < 128 * 32; idx += NTHREADS) {
        int c = idx & 31;
        int p = idx >> 5;
        int row = (c >> 3) * H + cta * 8 + (c & 7);
        float2 wv = *(const float2*)(W_ih + (size_t)row * INDIM + 2 * p);
        wpcT[p][c] = b2u(__floats2bfloat162_rn(wv.x, wv.y));
    }
    if (threadIdx.x < 32) {
        int c = threadIdx.x;
        int row = (c >> 3) * H + cta * 8 + (c & 7);
        bias_s[c] = b_ih[row] + b_hh[row];
    }
    for (int s = threadIdx.x; s < RING; s += NTHREADS) ring_tag[s] = -1;
    if (threadIdx.x == 0) scons = -1;
    __syncthreads();   // the ONLY full-CTA barrier

    if (wid < 4) {
        // ================= PRODUCER =================
        const int p = wid;
        for (int t = p; t < SEQ; t += 4) {
            unsigned spins = 0;
            while (scons < t - RING) {          // ring backpressure (bounded)
                __nanosleep(128);
                if (++spins >= (SPIN_CAP >> 6)) break;
            }

            // load x[t][lane*8 .. +7], convert to 4 bf16x2, stage for broadcast
            const float4* xp4 = (const float4*)&g_x[side][t][lane * 8];
            float4 v1 = __ldg(xp4);
            float4 v2 = __ldg(xp4 + 1);
            xstage[p][lane * 4 + 0] = b2u(__floats2bfloat162_rn(v1.x, v1.y));
            xstage[p][lane * 4 + 1] = b2u(__floats2bfloat162_rn(v1.z, v1.w));
            xstage[p][lane * 4 + 2] = b2u(__floats2bfloat162_rn(v2.x, v2.y));
            xstage[p][lane * 4 + 3] = b2u(__floats2bfloat162_rn(v2.z, v2.w));
            __syncwarp();

            // lane = col; dot over 128 k-pairs, 4 bf16x2 partial accumulators
            __nv_bfloat162 a0 = __floats2bfloat162_rn(0.f, 0.f);
            __nv_bfloat162 a1 = a0, a2 = a0, a3 = a0;
            #pragma unroll
            for (int s = 0; s < 32; s++) {
                uint4 xv = *(const uint4*)&xstage[p][s * 4];   // broadcast (16B)
                a0 = __hfma2(u2b(wpcT[s * 4 + 0][lane]), u2b(xv.x), a0);
                a1 = __hfma2(u2b(wpcT[s * 4 + 1][lane]), u2b(xv.y), a1);
                a2 = __hfma2(u2b(wpcT[s * 4 + 2][lane]), u2b(xv.z), a2);
                a3 = __hfma2(u2b(wpcT[s * 4 + 3][lane]), u2b(xv.w), a3);
            }
            float sum = (__low2float(a0) + __high2float(a0))
                      + (__low2float(a1) + __high2float(a1))
                      + (__low2float(a2) + __high2float(a2))
                      + (__low2float(a3) + __high2float(a3))
                      + bias_s[lane];
            ring[t & (RING - 1)][lane] = sum;
            __syncwarp();
            if (lane == 0) {
                asm volatile("membar.cta;" ::: "memory");
                ring_tag[t & (RING - 1)] = t;
            }
            __syncwarp();   // reads of xstage done before next iteration restages
        }
        return;
    }

    // ================= CONSUMER =================
    const int cw    = wid - 4;                  // 0..7
    const int jj    = cw;                       // unit within CTA
    const int j     = cta * 8 + jj;             // hidden unit 0..511
    const int tid_c = threadIdx.x - 128;        // 0..255

    const int mygate = lane >> 3;               // 0:i 1:f 2:g 3:o (8 lanes per gate)
    const int myidx  = lane & 7;                // h chunk index within gate

    // recurrent weights with the SAME rotation as the swizzled h reads:
    // q-th uint4 read covers h[myidx*64 + rot*8 .. +7], rot = (q+myidx)&7.
    unsigned w2[32];
    {
        const float2* row = (const float2*)(W_hh + (size_t)(mygate * H + j) * H);
        #pragma unroll
        for (int q = 0; q < 8; q++) {
            int rot = (q + myidx) & 7;
            #pragma unroll
            for (int i = 0; i < 4; i++) {
                float2 pv = row[myidx * 32 + rot * 4 + i];
                w2[q * 4 + i] = b2u(__floats2bfloat162_rn(pv.x, pv.y));
            }
        }
    }

    float c = 0.0f;                             // live in lane 0 only

    for (int t = 0; t < SEQ; t++) {
        const int rb = t & 1;
        const int slot = t & (RING - 1);

        // xp from SMEM ring (bounded wait; producers run ~64 steps ahead)
        unsigned spins = 0;
        while (ring_tag[slot] != t) {
            if (++spins >= SPIN_CAP) break;
        }
        float xg = ring[slot][mygate * 8 + jj];

        // poll own two packed units; stage bf16x2 word directly
        unsigned hp = poll_h2(&g_hp[side][rb][2 * tid_c], (unsigned)t);
        sh2[rb][tid_c] = hp;
        asm volatile("bar.sync 1, 256;" ::: "memory");
        if (tid_c == 0) scons = t;              // all consumers past ring read

        // swizzled conflict-free reads: q-th 16B chunk at word myidx*32 + rot*4.
        // For fixed q the 8 myidx rows hit 8 distinct offsets mod 128B.
        const uint4* hbase = (const uint4*)&sh2[rb][myidx * 32];
        __nv_bfloat162 a0 = __floats2bfloat162_rn(0.f, 0.f);
        __nv_bfloat162 a1 = a0, a2 = a0, a3 = a0;
        #pragma unroll
        for (int q = 0; q < 8; q++) {
            uint4 hv = hbase[(q + myidx) & 7];
            a0 = __hfma2(u2b(w2[q * 4 + 0]), u2b(hv.x), a0);
            a1 = __hfma2(u2b(w2[q * 4 + 1]), u2b(hv.y), a1);
            a2 = __hfma2(u2b(w2[q * 4 + 2]), u2b(hv.z), a2);
            a3 = __hfma2(u2b(w2[q * 4 + 3]), u2b(hv.w), a3);
        }
        float r = (__low2float(a0) + __high2float(a0))
                + (__low2float(a1) + __high2float(a1))
                + (__low2float(a2) + __high2float(a2))
                + (__low2float(a3) + __high2float(a3));

        // 3-round reduce within the 8-lane gate group
        r += __shfl_xor_sync(FULL, r, 4);
        r += __shfl_xor_sync(FULL, r, 2);
        r += __shfl_xor_sync(FULL, r, 1);

        // distributed activation: gate 2 -> tanh, else sigmoid
        float x = r + xg;
        bool is_tanh = (mygate == 2);
        float e = __expf(is_tanh ? (2.0f * x) : (-x));
        float num = is_tanh ? (e - 1.0f) : 1.0f;
        float act = num / (e + 1.0f);

        // lane 0 gathers gates: i lane 0, f lane 8, g lane 16, o lane 24
        float gf = __shfl_sync(FULL, act, 8);
        float gg = __shfl_sync(FULL, act, 16);
        float go = __shfl_sync(FULL, act, 24);
        if (lane == 0) {
            c = gf * c + act * gg;              // act = gi in lane 0
            float hval = go * fast_tanh(c);
            store_h(&g_hp[side][rb ^ 1][j], hval, (unsigned)(t + 1));
        }
    }

    // Final: block 0's consumers poll both sides' final tags (SEQ=2048) and reduce.
    if (blockIdx.x == 0) {
        unsigned lp = poll_h2(&g_hp[0][0][2 * tid_c], (unsigned)SEQ);
        unsigned rp = poll_h2(&g_hp[1][0][2 * tid_c], (unsigned)SEQ);
        __nv_bfloat162 lv = u2b(lp), rv = u2b(rp);
        float sv = fabsf(__low2float(lv) - __low2float(rv))
                 + fabsf(__high2float(lv) - __high2float(rv));
        #pragma unroll
        for (int off = 16; off > 0; off >>= 1)
            sv += __shfl_xor_sync(FULL, sv, off);
        if (lane == 0) sred[cw] = sv;
        asm volatile("bar.sync 1, 256;" ::: "memory");
        if (tid_c == 0) {
            float s = 0.0f;
            #pragma unroll
            for (int wdx = 0; wdx < 8; wdx++) s += sred[wdx];
            out[0] = expf(-s);
        }
    }
}

// ---------------- launch ----------------
extern "C" void kernel_launch(void* const* d_in, const int* in_sizes, int n_in,
                              void* d_out, int out_size) {
    const int* lidx = (const int*)d_in[0];
    const int* ridx = (const int*)d_in[1];
    const float* emb  = (const float*)d_in[2];
    const float* W_ih = (const float*)d_in[3];
    const float* W_hh = (const float*)d_in[4];
    const float* b_ih = (const float*)d_in[5];
    const float* b_hh = (const float*)d_in[6];
    float* out = (float*)d_out;

    init_gather<<<4096, 256>>>(lidx, ridx, emb);
    scan_kernel<<<TOTAL_CTAS, NTHREADS>>>(W_ih, W_hh, b_ih, b_hh, out);
}